// round 7
// baseline (speedup 1.0000x reference)
#include <cuda_runtime.h>
#include <cuda_fp16.h>
#include <math.h>
#include <stdint.h>

#define NN 8
#define CC 1024
#define BB 2048
#define EPS 1e-12f

// ---- scratch (device globals; no allocation allowed) ----
__device__ __half g_Kh[(size_t)NN * CC * BB];   // K [o][b] fp16
__device__ __half g_Qh[(size_t)NN * CC * BB];   // Q [o][b] fp16
__device__ __half g_Y [(size_t)NN * BB * BB];   // Y [b][k'] fp16, then SM in place
__device__ __half g_Xh[(size_t)NN * CC * BB];   // X fp16 [c][b]
__device__ __half g_Wkh[CC * CC];
__device__ __half g_Wqh[CC * CC];
__device__ float  g_DK2[NN * BB];
__device__ float  g_DQ2[NN * BB];

// ---------------------------------------------------------------------------
__device__ __forceinline__ void cp16s(uint32_t s, const __half* g) {
    asm volatile("cp.async.cg.shared.global [%0], [%1], 16;" :: "r"(s), "l"(g));
}
#define CP_COMMIT() asm volatile("cp.async.commit_group;")

__device__ __forceinline__ void ldm4(uint32_t (&r)[4], uint32_t a) {
    asm volatile("ldmatrix.sync.aligned.m8n8.x4.shared.b16 {%0,%1,%2,%3}, [%4];"
                 : "=r"(r[0]), "=r"(r[1]), "=r"(r[2]), "=r"(r[3]) : "r"(a));
}
__device__ __forceinline__ void ldm4t(uint32_t (&r)[4], uint32_t a) {
    asm volatile("ldmatrix.sync.aligned.m8n8.x4.trans.shared.b16 {%0,%1,%2,%3}, [%4];"
                 : "=r"(r[0]), "=r"(r[1]), "=r"(r[2]), "=r"(r[3]) : "r"(a));
}
__device__ __forceinline__ void mma16(float (&d)[4], const uint32_t (&a)[4],
                                      const uint32_t (&b)[2]) {
    asm volatile(
        "mma.sync.aligned.m16n8k16.row.col.f32.f16.f16.f32 "
        "{%0,%1,%2,%3}, {%4,%5,%6,%7}, {%8,%9}, {%0,%1,%2,%3};"
        : "+f"(d[0]), "+f"(d[1]), "+f"(d[2]), "+f"(d[3])
        : "r"(a[0]), "r"(a[1]), "r"(a[2]), "r"(a[3]), "r"(b[0]), "r"(b[1]));
}

// ===========================================================================
// FP16 warp-MMA GEMM: CTA 128x256, 8 warps (2m x 4n), warp tile 64x64,
// BK=32, 3-stage cp.async, ldmatrix fragment loads.
// D[m][n] = sum_k A[m][k] * B[k][n]
//   A: row-major [m][k] (AKM=false) or k-major [k][m] (AKM=true) in gmem.
//   B: [k][n] n-contiguous in gmem.
// MODE 0: proj  (out half: acc + bias[m])
// MODE 1: score (out half: acc * rsqrt(max(dq2[m]*dk2[n], EPS)))
// MODE 2: mix   (out float: acc)
// ===========================================================================
#define BK 32
#define ARM_STR 40     // A row-major smem stride (halves): 32 + 8 pad
#define AKM_STR 136    // A k-major smem stride (halves): 128 + 8 pad
#define B_STR 264      // B smem stride (halves): 256 + 8 pad
#define NSTAGE 3

template <int MODE, int KDIM, bool AKM, typename OutT>
__global__ __launch_bounds__(256)
void gemm_h(const __half* __restrict__ A, int lda, size_t strA,
            const __half* __restrict__ B, int ldb, size_t strB,
            OutT* __restrict__ C, int ldc, size_t strC,
            const float* __restrict__ bias,
            const float* __restrict__ dq2_all,
            const float* __restrict__ dk2_all)
{
    constexpr int SA = AKM ? BK * AKM_STR : 128 * ARM_STR;
    constexpr int SB = BK * B_STR;
    __shared__ __half sA[NSTAGE][SA];
    __shared__ __half sB[NSTAGE][SB];
    __shared__ float s_dk[256];

    const int nb = blockIdx.z;
    const __half* An = A + (size_t)nb * strA;
    const __half* Bn = B + (size_t)nb * strB;
    OutT* Cn = C + (size_t)nb * strC;
    const int row0 = blockIdx.y * 128;
    const int col0 = blockIdx.x * 256;

    const int tid = threadIdx.x;
    const int lane = tid & 31;
    const int wid = tid >> 5;
    const int wm = wid >> 2;    // 0..1 (64-row slab)
    const int wn = wid & 3;     // 0..3 (64-col slab)
    const int l7 = lane & 7;
    const int g = lane >> 3;

    if (MODE == 1)
        s_dk[tid] = dk2_all[(size_t)nb * BB + col0 + tid];

    float acc[4][8][4] = {};

    auto ldA = [&](int st, int kt) {
        uint32_t sb = (uint32_t)__cvta_generic_to_shared(&sA[st][0]);
        if (!AKM) {
            #pragma unroll
            for (int i = tid; i < 512; i += 256) {       // 128 rows x 4 chunks
                int m = i >> 2, c = i & 3;
                cp16s(sb + (m * ARM_STR + c * 8) * 2,
                      An + (size_t)(row0 + m) * lda + kt * BK + c * 8);
            }
        } else {
            #pragma unroll
            for (int i = tid; i < 512; i += 256) {       // 32 k-rows x 16 chunks
                int k = i >> 4, c = i & 15;
                cp16s(sb + (k * AKM_STR + c * 8) * 2,
                      An + (size_t)(kt * BK + k) * lda + row0 + c * 8);
            }
        }
    };
    auto ldB = [&](int st, int kt) {
        uint32_t sb = (uint32_t)__cvta_generic_to_shared(&sB[st][0]);
        #pragma unroll
        for (int i = tid; i < 1024; i += 256) {          // 32 k-rows x 32 chunks
            int k = i >> 5, c = i & 31;
            cp16s(sb + (k * B_STR + c * 8) * 2,
                  Bn + (size_t)(kt * BK + k) * ldb + col0 + c * 8);
        }
    };

    constexpr int KT = KDIM / BK;

    ldA(0, 0); ldB(0, 0); CP_COMMIT();
    ldA(1, 1); ldB(1, 1); CP_COMMIT();

    for (int kt = 0; kt < KT; kt++) {
        const int buf = kt % NSTAGE;
        if (kt + 2 < KT) {
            const int nst = (kt + 2) % NSTAGE;
            ldA(nst, kt + 2);
            ldB(nst, kt + 2);
            CP_COMMIT();
            asm volatile("cp.async.wait_group 2;");
        } else if (kt + 1 < KT) {
            asm volatile("cp.async.wait_group 1;");
        } else {
            asm volatile("cp.async.wait_group 0;");
        }
        __syncthreads();

        uint32_t aA = (uint32_t)__cvta_generic_to_shared(&sA[buf][0]);
        uint32_t aB = (uint32_t)__cvta_generic_to_shared(&sB[buf][0]);

        #pragma unroll
        for (int ks = 0; ks < 2; ks++) {
            uint32_t af[4][4];
            uint32_t bf[8][2];

            // A fragments (m64 x k16): 4 x ldmatrix.x4
            #pragma unroll
            for (int mi = 0; mi < 4; mi++) {
                if (!AKM) {
                    int m = wm * 64 + mi * 16 + l7 + (g & 1) * 8;
                    int k = ks * 16 + (g >> 1) * 8;
                    ldm4(af[mi], aA + (m * ARM_STR + k) * 2);
                } else {
                    int k = ks * 16 + (g >> 1) * 8 + l7;
                    int m = wm * 64 + mi * 16 + (g & 1) * 8;
                    ldm4t(af[mi], aA + (k * AKM_STR + m) * 2);
                }
            }
            // B fragments (k16 x n64): 4 x ldmatrix.x4.trans
            #pragma unroll
            for (int j = 0; j < 4; j++) {
                int k = ks * 16 + (g & 1) * 8 + l7;
                int nn = wn * 64 + j * 16 + (g >> 1) * 8;
                uint32_t r[4];
                ldm4t(r, aB + (k * B_STR + nn) * 2);
                bf[2 * j][0] = r[0];      bf[2 * j][1] = r[1];
                bf[2 * j + 1][0] = r[2];  bf[2 * j + 1][1] = r[3];
            }
            #pragma unroll
            for (int mi = 0; mi < 4; mi++)
                #pragma unroll
                for (int ni = 0; ni < 8; ni++)
                    mma16(acc[mi][ni], af[mi], bf[ni]);
        }
        __syncthreads();
    }

    // ---- epilogue ----
    const int lr = lane >> 2, lc = lane & 3;
    const float* dq2 = (MODE == 1) ? dq2_all + (size_t)nb * BB : nullptr;

    #pragma unroll
    for (int mi = 0; mi < 4; mi++) {
        const int m = row0 + wm * 64 + mi * 16 + lr;
        float b0 = 0.f, b1 = 0.f, dqa = 0.f, dqb = 0.f;
        if (MODE == 0) { b0 = bias[m]; b1 = bias[m + 8]; }
        if (MODE == 1) { dqa = dq2[m]; dqb = dq2[m + 8]; }

        #pragma unroll
        for (int ni = 0; ni < 8; ni++) {
            const int cl = wn * 64 + ni * 8 + 2 * lc;   // local col in [0,256)
            const int nn = col0 + cl;
            float v0 = acc[mi][ni][0], v1 = acc[mi][ni][1];
            float v2 = acc[mi][ni][2], v3 = acc[mi][ni][3];
            if (MODE == 0) {
                v0 += b0; v1 += b0; v2 += b1; v3 += b1;
            } else if (MODE == 1) {
                float dk0 = s_dk[cl], dk1 = s_dk[cl + 1];
                v0 *= rsqrtf(fmaxf(dqa * dk0, EPS));
                v1 *= rsqrtf(fmaxf(dqa * dk1, EPS));
                v2 *= rsqrtf(fmaxf(dqb * dk0, EPS));
                v3 *= rsqrtf(fmaxf(dqb * dk1, EPS));
            }
            if (MODE == 2) {
                float* p0 = (float*)&Cn[(size_t)m * ldc + nn];
                float* p1 = (float*)&Cn[(size_t)(m + 8) * ldc + nn];
                *reinterpret_cast<float2*>(p0) = make_float2(v0, v1);
                *reinterpret_cast<float2*>(p1) = make_float2(v2, v3);
            } else {
                __half* p0 = (__half*)&Cn[(size_t)m * ldc + nn];
                __half* p1 = (__half*)&Cn[(size_t)(m + 8) * ldc + nn];
                *reinterpret_cast<__half2*>(p0) = __floats2half2_rn(v0, v1);
                *reinterpret_cast<__half2*>(p1) = __floats2half2_rn(v2, v3);
            }
        }
    }
}

// ---------------------------------------------------------------------------
__global__ __launch_bounds__(256)
void to_half_kernel(const float* __restrict__ in, __half* __restrict__ out, int n4)
{
    int i = blockIdx.x * 256 + threadIdx.x;
    int stride = gridDim.x * 256;
    for (; i < n4; i += stride) {
        float4 v = reinterpret_cast<const float4*>(in)[i];
        __half2* o = reinterpret_cast<__half2*>(out) + 2 * i;
        o[0] = __floats2half2_rn(v.x, v.y);
        o[1] = __floats2half2_rn(v.z, v.w);
    }
}

// ---------------------------------------------------------------------------
// Column squared norms of K and Q (fp16 in, fp32 sums)
// ---------------------------------------------------------------------------
__global__ __launch_bounds__(256)
void sq_kernel()
{
    int idx = blockIdx.x * 256 + threadIdx.x;      // over NN * BB/2
    int n = idx / (BB / 2);
    int b2 = idx % (BB / 2);
    const __half2* Kn = (const __half2*)(g_Kh + (size_t)n * CC * BB) + b2;
    const __half2* Qn = (const __half2*)(g_Qh + (size_t)n * CC * BB) + b2;
    float skx = 0.f, sky = 0.f, sqx = 0.f, sqy = 0.f;
    #pragma unroll 8
    for (int c = 0; c < CC; c++) {
        float2 k2 = __half22float2(Kn[(size_t)c * (BB / 2)]);
        float2 q2 = __half22float2(Qn[(size_t)c * (BB / 2)]);
        skx = fmaf(k2.x, k2.x, skx); sky = fmaf(k2.y, k2.y, sky);
        sqx = fmaf(q2.x, q2.x, sqx); sqy = fmaf(q2.y, q2.y, sqy);
    }
    g_DK2[n * BB + 2 * b2] = skx;  g_DK2[n * BB + 2 * b2 + 1] = sky;
    g_DQ2[n * BB + 2 * b2] = sqx;  g_DQ2[n * BB + 2 * b2 + 1] = sqy;
}

// ---------------------------------------------------------------------------
// exp(x) for x in [-1.05, 1.05] via Taylor to x^9 (rel err ~3e-7) — pure FMA.
// Valid because cosine scores are bounded by 1.
// ---------------------------------------------------------------------------
__device__ __forceinline__ float exp_poly(float x)
{
    float r = fmaf(x, 1.f / 9.f, 1.f);
    r = fmaf(r * x, 1.f / 8.f, 1.f);
    r = fmaf(r * x, 1.f / 7.f, 1.f);
    r = fmaf(r * x, 1.f / 6.f, 1.f);
    r = fmaf(r * x, 1.f / 5.f, 1.f);
    r = fmaf(r * x, 1.f / 4.f, 1.f);
    r = fmaf(r * x, 1.f / 3.f, 1.f);
    r = fmaf(r * x, 0.5f, 1.f);
    return fmaf(r, x, 1.f);
}

// ---------------------------------------------------------------------------
// Softmax over b (axis=1) of Y[n][b][k'], in place, fp16, no max-shift.
// ---------------------------------------------------------------------------
__global__ __launch_bounds__(256)
void softmax_kernel()
{
    const int n = blockIdx.y;
    const int k2 = blockIdx.x * 256 + threadIdx.x;   // over BB/2
    __half2* Yn = (__half2*)(g_Y + (size_t)n * BB * BB) + k2;

    float sx = 0.f, sy = 0.f;
    #pragma unroll 4
    for (int b = 0; b < BB; b++) {
        float2 v = __half22float2(Yn[(size_t)b * (BB / 2)]);
        sx += exp_poly(v.x);
        sy += exp_poly(v.y);
    }
    const float ix = 1.f / sx, iy = 1.f / sy;
    #pragma unroll 4
    for (int b = 0; b < BB; b++) {
        float2 v = __half22float2(Yn[(size_t)b * (BB / 2)]);
        Yn[(size_t)b * (BB / 2)] =
            __floats2half2_rn(exp_poly(v.x) * ix, exp_poly(v.y) * iy);
    }
}

// ---------------------------------------------------------------------------
extern "C" void kernel_launch(void* const* d_in, const int* in_sizes, int n_in,
                              void* d_out, int out_size)
{
    const float* X    = (const float*)d_in[0];
    const float* Wk_w = (const float*)d_in[1];
    const float* Wk_b = (const float*)d_in[2];
    const float* Wq_w = (const float*)d_in[3];
    const float* Wq_b = (const float*)d_in[4];
    float* Z = (float*)d_out;

    __half* Kh;  cudaGetSymbolAddress((void**)&Kh,  g_Kh);
    __half* Qh;  cudaGetSymbolAddress((void**)&Qh,  g_Qh);
    __half* Yd;  cudaGetSymbolAddress((void**)&Yd,  g_Y);
    __half* Xh;  cudaGetSymbolAddress((void**)&Xh,  g_Xh);
    __half* Wkh; cudaGetSymbolAddress((void**)&Wkh, g_Wkh);
    __half* Wqh; cudaGetSymbolAddress((void**)&Wqh, g_Wqh);
    float* DK2;  cudaGetSymbolAddress((void**)&DK2, g_DK2);
    float* DQ2;  cudaGetSymbolAddress((void**)&DQ2, g_DQ2);

    const size_t sXn = (size_t)CC * BB;
    const size_t sYn = (size_t)BB * BB;

    // 0) convert operands to fp16
    to_half_kernel<<<2048, 256>>>(X, Xh, (int)(NN * sXn / 4));
    to_half_kernel<<<256, 256>>>(Wk_w, Wkh, CC * CC / 4);
    to_half_kernel<<<256, 256>>>(Wq_w, Wqh, CC * CC / 4);

    // 1) projections: K/Q[o][b] = W[o][c] @ X[c][b] + bias
    gemm_h<0, CC, false, __half><<<dim3(BB / 256, CC / 128, NN), 256>>>(
        Wkh, CC, 0, Xh, BB, sXn, Kh, BB, sXn, Wk_b, nullptr, nullptr);
    gemm_h<0, CC, false, __half><<<dim3(BB / 256, CC / 128, NN), 256>>>(
        Wqh, CC, 0, Xh, BB, sXn, Qh, BB, sXn, Wq_b, nullptr, nullptr);

    // 2) squared norms
    sq_kernel<<<(NN * BB / 2) / 256, 256>>>();

    // 3) scores: Y[b][k'] = sum_c Q[c][b] K[c][k'] * rsqrt(dq2[b] dk2[k'])
    gemm_h<1, CC, true, __half><<<dim3(BB / 256, BB / 128, NN), 256>>>(
        Qh, BB, sXn, Kh, BB, sXn, Yd, BB, sYn, nullptr, DQ2, DK2);

    // 4) softmax over b (query axis), in place
    softmax_kernel<<<dim3(BB / 512, NN), 256>>>();

    // 5) mix: Z[c][k'] = sum_b X[c][b] SM[b][k']
    gemm_h<2, BB, false, float><<<dim3(BB / 256, CC / 128, NN), 256>>>(
        Xh, BB, sXn, Yd, BB, sYn, Z, BB, sXn, nullptr, nullptr, nullptr);
}

// round 8
// speedup vs baseline: 1.1197x; 1.1197x over previous
#include <cuda_runtime.h>
#include <cuda_fp16.h>
#include <math.h>
#include <stdint.h>

#define NN 8
#define CC 1024
#define BB 2048
#define EPS 1e-12f

// ---- scratch (device globals; no allocation allowed) ----
__device__ __half g_Kh[(size_t)NN * CC * BB];   // K [o][b] fp16
__device__ __half g_Qh[(size_t)NN * CC * BB];   // Q [o][b] fp16
__device__ __half g_Y [(size_t)NN * BB * BB];   // Y [b][k'] fp16, then SM in place
__device__ __half g_Xh[(size_t)NN * CC * BB];   // X fp16 [c][b]
__device__ __half g_Wkh[CC * CC];
__device__ __half g_Wqh[CC * CC];
__device__ float  g_DK2[NN * BB];
__device__ float  g_DQ2[NN * BB];

// ---------------------------------------------------------------------------
__device__ __forceinline__ void cp16s(uint32_t s, const __half* g) {
    asm volatile("cp.async.cg.shared.global [%0], [%1], 16;" :: "r"(s), "l"(g));
}
#define CP_COMMIT() asm volatile("cp.async.commit_group;")

__device__ __forceinline__ void ldm4(uint32_t (&r)[4], uint32_t a) {
    asm volatile("ldmatrix.sync.aligned.m8n8.x4.shared.b16 {%0,%1,%2,%3}, [%4];"
                 : "=r"(r[0]), "=r"(r[1]), "=r"(r[2]), "=r"(r[3]) : "r"(a));
}
__device__ __forceinline__ void ldm4t(uint32_t (&r)[4], uint32_t a) {
    asm volatile("ldmatrix.sync.aligned.m8n8.x4.trans.shared.b16 {%0,%1,%2,%3}, [%4];"
                 : "=r"(r[0]), "=r"(r[1]), "=r"(r[2]), "=r"(r[3]) : "r"(a));
}
__device__ __forceinline__ void mma16(float (&d)[4], const uint32_t (&a)[4],
                                      const uint32_t (&b)[2]) {
    asm volatile(
        "mma.sync.aligned.m16n8k16.row.col.f32.f16.f16.f32 "
        "{%0,%1,%2,%3}, {%4,%5,%6,%7}, {%8,%9}, {%0,%1,%2,%3};"
        : "+f"(d[0]), "+f"(d[1]), "+f"(d[2]), "+f"(d[3])
        : "r"(a[0]), "r"(a[1]), "r"(a[2]), "r"(a[3]), "r"(b[0]), "r"(b[1]));
}

// ===========================================================================
// FP16 warp-MMA GEMM: CTA 128x128, 4 warps (2m x 2n), warp tile 64x64,
// BK=32, 2-stage cp.async, ldmatrix fragment loads, 3 CTAs/SM.
// D[m][n] = sum_k A[m][k] * B[k][n]
//   A: row-major [m][k] (AKM=false) or k-major [k][m] (AKM=true) in gmem.
//   B: [k][n] n-contiguous in gmem.
// MODE 0: proj  (out half: acc + bias[m])
// MODE 1: score (out half: acc * rsqrt(max(dq2[m]*dk2[n], EPS)))
// MODE 2: mix   (out float: acc)
// ===========================================================================
#define BK 32
#define ARM_STR 40     // A row-major smem stride (halves): 32 + 8 pad
#define KM_STR 136     // k-major / B smem stride (halves): 128 + 8 pad

template <int MODE, int KDIM, bool AKM, typename OutT>
__global__ __launch_bounds__(128, 3)
void gemm_h(const __half* __restrict__ A, int lda, size_t strA,
            const __half* __restrict__ B, int ldb, size_t strB,
            OutT* __restrict__ C, int ldc, size_t strC,
            const float* __restrict__ bias,
            const float* __restrict__ dq2_all,
            const float* __restrict__ dk2_all)
{
    constexpr int SA = AKM ? BK * KM_STR : 128 * ARM_STR;
    constexpr int SB = BK * KM_STR;
    __shared__ __half sA[2][SA];
    __shared__ __half sB[2][SB];
    __shared__ float s_dk[128];

    const int nb = blockIdx.z;
    const __half* An = A + (size_t)nb * strA;
    const __half* Bn = B + (size_t)nb * strB;
    OutT* Cn = C + (size_t)nb * strC;
    const int row0 = blockIdx.y * 128;
    const int col0 = blockIdx.x * 128;

    const int tid = threadIdx.x;
    const int lane = tid & 31;
    const int wid = tid >> 5;
    const int wm = wid >> 1;    // 0..1 (64-row slab)
    const int wn = wid & 1;     // 0..1 (64-col slab)
    const int l7 = lane & 7;
    const int g = lane >> 3;

    if (MODE == 1)
        s_dk[tid] = dq2_all ? dk2_all[(size_t)nb * BB + col0 + tid] : 0.f;

    float acc[4][8][4] = {};

    auto ldA = [&](int st, int kt) {
        uint32_t sb = (uint32_t)__cvta_generic_to_shared(&sA[st][0]);
        if (!AKM) {
            #pragma unroll
            for (int i = tid; i < 512; i += 128) {       // 128 rows x 4 chunks
                int m = i >> 2, c = i & 3;
                cp16s(sb + (m * ARM_STR + c * 8) * 2,
                      An + (size_t)(row0 + m) * lda + kt * BK + c * 8);
            }
        } else {
            #pragma unroll
            for (int i = tid; i < 512; i += 128) {       // 32 k-rows x 16 chunks
                int k = i >> 4, c = i & 15;
                cp16s(sb + (k * KM_STR + c * 8) * 2,
                      An + (size_t)(kt * BK + k) * lda + row0 + c * 8);
            }
        }
    };
    auto ldB = [&](int st, int kt) {
        uint32_t sb = (uint32_t)__cvta_generic_to_shared(&sB[st][0]);
        #pragma unroll
        for (int i = tid; i < 512; i += 128) {
            int k = i >> 4, c = i & 15;
            cp16s(sb + (k * KM_STR + c * 8) * 2,
                  Bn + (size_t)(kt * BK + k) * ldb + col0 + c * 8);
        }
    };

    constexpr int KT = KDIM / BK;

    ldA(0, 0); ldB(0, 0); CP_COMMIT();

    for (int kt = 0; kt < KT; kt++) {
        const int buf = kt & 1;
        if (kt + 1 < KT) {
            ldA(buf ^ 1, kt + 1);
            ldB(buf ^ 1, kt + 1);
            CP_COMMIT();
            asm volatile("cp.async.wait_group 1;");
        } else {
            asm volatile("cp.async.wait_group 0;");
        }
        __syncthreads();

        uint32_t aA = (uint32_t)__cvta_generic_to_shared(&sA[buf][0]);
        uint32_t aB = (uint32_t)__cvta_generic_to_shared(&sB[buf][0]);

        #pragma unroll
        for (int ks = 0; ks < 2; ks++) {
            uint32_t af[4][4];
            uint32_t bf[8][2];

            // A fragments (m64 x k16): 4 x ldmatrix.x4
            #pragma unroll
            for (int mi = 0; mi < 4; mi++) {
                if (!AKM) {
                    int m = wm * 64 + mi * 16 + l7 + (g & 1) * 8;
                    int k = ks * 16 + (g >> 1) * 8;
                    ldm4(af[mi], aA + (m * ARM_STR + k) * 2);
                } else {
                    int k = ks * 16 + (g >> 1) * 8 + l7;
                    int m = wm * 64 + mi * 16 + (g & 1) * 8;
                    ldm4t(af[mi], aA + (k * KM_STR + m) * 2);
                }
            }
            // B fragments (k16 x n64): 4 x ldmatrix.x4.trans
            #pragma unroll
            for (int j = 0; j < 4; j++) {
                int k = ks * 16 + (g & 1) * 8 + l7;
                int nn = wn * 64 + j * 16 + (g >> 1) * 8;
                uint32_t r[4];
                ldm4t(r, aB + (k * KM_STR + nn) * 2);
                bf[2 * j][0] = r[0];      bf[2 * j][1] = r[1];
                bf[2 * j + 1][0] = r[2];  bf[2 * j + 1][1] = r[3];
            }
            #pragma unroll
            for (int mi = 0; mi < 4; mi++)
                #pragma unroll
                for (int ni = 0; ni < 8; ni++)
                    mma16(acc[mi][ni], af[mi], bf[ni]);
        }
        __syncthreads();
    }

    // ---- epilogue ----
    const int lr = lane >> 2, lc = lane & 3;
    const float* dq2 = (MODE == 1) ? dq2_all + (size_t)nb * BB : nullptr;

    #pragma unroll
    for (int mi = 0; mi < 4; mi++) {
        const int m = row0 + wm * 64 + mi * 16 + lr;
        float b0 = 0.f, b1 = 0.f, dqa = 0.f, dqb = 0.f;
        if (MODE == 0) { b0 = bias[m]; b1 = bias[m + 8]; }
        if (MODE == 1) { dqa = dq2[m]; dqb = dq2[m + 8]; }

        #pragma unroll
        for (int ni = 0; ni < 8; ni++) {
            const int cl = wn * 64 + ni * 8 + 2 * lc;   // local col in [0,128)
            const int nn = col0 + cl;
            float v0 = acc[mi][ni][0], v1 = acc[mi][ni][1];
            float v2 = acc[mi][ni][2], v3 = acc[mi][ni][3];
            if (MODE == 0) {
                v0 += b0; v1 += b0; v2 += b1; v3 += b1;
            } else if (MODE == 1) {
                float dk0 = s_dk[cl], dk1 = s_dk[cl + 1];
                v0 *= rsqrtf(fmaxf(dqa * dk0, EPS));
                v1 *= rsqrtf(fmaxf(dqa * dk1, EPS));
                v2 *= rsqrtf(fmaxf(dqb * dk0, EPS));
                v3 *= rsqrtf(fmaxf(dqb * dk1, EPS));
            }
            if (MODE == 2) {
                float* p0 = (float*)&Cn[(size_t)m * ldc + nn];
                float* p1 = (float*)&Cn[(size_t)(m + 8) * ldc + nn];
                *reinterpret_cast<float2*>(p0) = make_float2(v0, v1);
                *reinterpret_cast<float2*>(p1) = make_float2(v2, v3);
            } else {
                __half* p0 = (__half*)&Cn[(size_t)m * ldc + nn];
                __half* p1 = (__half*)&Cn[(size_t)(m + 8) * ldc + nn];
                *reinterpret_cast<__half2*>(p0) = __floats2half2_rn(v0, v1);
                *reinterpret_cast<__half2*>(p1) = __floats2half2_rn(v2, v3);
            }
        }
    }
}

// ---------------------------------------------------------------------------
__global__ __launch_bounds__(256)
void to_half_kernel(const float* __restrict__ in, __half* __restrict__ out, int n4)
{
    int i = blockIdx.x * 256 + threadIdx.x;
    int stride = gridDim.x * 256;
    for (; i < n4; i += stride) {
        float4 v = reinterpret_cast<const float4*>(in)[i];
        __half2* o = reinterpret_cast<__half2*>(out) + 2 * i;
        o[0] = __floats2half2_rn(v.x, v.y);
        o[1] = __floats2half2_rn(v.z, v.w);
    }
}

// ---------------------------------------------------------------------------
// Column squared norms of K and Q (fp16 in, fp32 sums)
// ---------------------------------------------------------------------------
__global__ __launch_bounds__(256)
void sq_kernel()
{
    int idx = blockIdx.x * 256 + threadIdx.x;      // over NN * BB/2
    int n = idx / (BB / 2);
    int b2 = idx % (BB / 2);
    const __half2* Kn = (const __half2*)(g_Kh + (size_t)n * CC * BB) + b2;
    const __half2* Qn = (const __half2*)(g_Qh + (size_t)n * CC * BB) + b2;
    float skx = 0.f, sky = 0.f, sqx = 0.f, sqy = 0.f;
    #pragma unroll 8
    for (int c = 0; c < CC; c++) {
        float2 k2 = __half22float2(Kn[(size_t)c * (BB / 2)]);
        float2 q2 = __half22float2(Qn[(size_t)c * (BB / 2)]);
        skx = fmaf(k2.x, k2.x, skx); sky = fmaf(k2.y, k2.y, sky);
        sqx = fmaf(q2.x, q2.x, sqx); sqy = fmaf(q2.y, q2.y, sqy);
    }
    g_DK2[n * BB + 2 * b2] = skx;  g_DK2[n * BB + 2 * b2 + 1] = sky;
    g_DQ2[n * BB + 2 * b2] = sqx;  g_DQ2[n * BB + 2 * b2 + 1] = sqy;
}

// ---------------------------------------------------------------------------
// exp(x) for x in [-1.05, 1.05] via Taylor to x^9 (rel err ~3e-7) — pure FMA.
// Valid because cosine scores are bounded by 1.
// ---------------------------------------------------------------------------
__device__ __forceinline__ float exp_poly(float x)
{
    float r = fmaf(x, 1.f / 9.f, 1.f);
    r = fmaf(r * x, 1.f / 8.f, 1.f);
    r = fmaf(r * x, 1.f / 7.f, 1.f);
    r = fmaf(r * x, 1.f / 6.f, 1.f);
    r = fmaf(r * x, 1.f / 5.f, 1.f);
    r = fmaf(r * x, 1.f / 4.f, 1.f);
    r = fmaf(r * x, 1.f / 3.f, 1.f);
    r = fmaf(r * x, 0.5f, 1.f);
    return fmaf(r, x, 1.f);
}

// ---------------------------------------------------------------------------
// Softmax over b (axis=1) of Y[n][b][k'], in place, fp16, no max-shift.
// ---------------------------------------------------------------------------
__global__ __launch_bounds__(256)
void softmax_kernel()
{
    const int n = blockIdx.y;
    const int k2 = blockIdx.x * 256 + threadIdx.x;   // over BB/2
    __half2* Yn = (__half2*)(g_Y + (size_t)n * BB * BB) + k2;

    float sx = 0.f, sy = 0.f;
    #pragma unroll 4
    for (int b = 0; b < BB; b++) {
        float2 v = __half22float2(Yn[(size_t)b * (BB / 2)]);
        sx += exp_poly(v.x);
        sy += exp_poly(v.y);
    }
    const float ix = 1.f / sx, iy = 1.f / sy;
    #pragma unroll 4
    for (int b = 0; b < BB; b++) {
        float2 v = __half22float2(Yn[(size_t)b * (BB / 2)]);
        Yn[(size_t)b * (BB / 2)] =
            __floats2half2_rn(exp_poly(v.x) * ix, exp_poly(v.y) * iy);
    }
}

// ---------------------------------------------------------------------------
extern "C" void kernel_launch(void* const* d_in, const int* in_sizes, int n_in,
                              void* d_out, int out_size)
{
    const float* X    = (const float*)d_in[0];
    const float* Wk_w = (const float*)d_in[1];
    const float* Wk_b = (const float*)d_in[2];
    const float* Wq_w = (const float*)d_in[3];
    const float* Wq_b = (const float*)d_in[4];
    float* Z = (float*)d_out;

    __half* Kh;  cudaGetSymbolAddress((void**)&Kh,  g_Kh);
    __half* Qh;  cudaGetSymbolAddress((void**)&Qh,  g_Qh);
    __half* Yd;  cudaGetSymbolAddress((void**)&Yd,  g_Y);
    __half* Xh;  cudaGetSymbolAddress((void**)&Xh,  g_Xh);
    __half* Wkh; cudaGetSymbolAddress((void**)&Wkh, g_Wkh);
    __half* Wqh; cudaGetSymbolAddress((void**)&Wqh, g_Wqh);
    float* DK2;  cudaGetSymbolAddress((void**)&DK2, g_DK2);
    float* DQ2;  cudaGetSymbolAddress((void**)&DQ2, g_DQ2);

    const size_t sXn = (size_t)CC * BB;
    const size_t sYn = (size_t)BB * BB;

    // 0) convert operands to fp16
    to_half_kernel<<<2048, 256>>>(X, Xh, (int)(NN * sXn / 4));
    to_half_kernel<<<256, 256>>>(Wk_w, Wkh, CC * CC / 4);
    to_half_kernel<<<256, 256>>>(Wq_w, Wqh, CC * CC / 4);

    // 1) projections: K/Q[o][b] = W[o][c] @ X[c][b] + bias
    gemm_h<0, CC, false, __half><<<dim3(BB / 128, CC / 128, NN), 128>>>(
        Wkh, CC, 0, Xh, BB, sXn, Kh, BB, sXn, Wk_b, nullptr, nullptr);
    gemm_h<0, CC, false, __half><<<dim3(BB / 128, CC / 128, NN), 128>>>(
        Wqh, CC, 0, Xh, BB, sXn, Qh, BB, sXn, Wq_b, nullptr, nullptr);

    // 2) squared norms
    sq_kernel<<<(NN * BB / 2) / 256, 256>>>();

    // 3) scores: Y[b][k'] = sum_c Q[c][b] K[c][k'] * rsqrt(dq2[b] dk2[k'])
    gemm_h<1, CC, true, __half><<<dim3(BB / 128, BB / 128, NN), 128>>>(
        Qh, BB, sXn, Kh, BB, sXn, Yd, BB, sYn, nullptr, DQ2, DK2);

    // 4) softmax over b (query axis), in place
    softmax_kernel<<<dim3(BB / 512, NN), 256>>>();

    // 5) mix: Z[c][k'] = sum_b X[c][b] SM[b][k']
    gemm_h<2, BB, false, float><<<dim3(BB / 128, CC / 128, NN), 128>>>(
        Xh, BB, sXn, Yd, BB, sYn, Z, BB, sXn, nullptr, nullptr, nullptr);
}

// round 9
// speedup vs baseline: 1.8742x; 1.6739x over previous
#include <cuda_runtime.h>
#include <cuda_fp16.h>
#include <math.h>
#include <stdint.h>

#define NN 8
#define CC 1024
#define BB 2048
#define EPS 1e-12f

// ---- scratch (device globals; no allocation allowed) ----
__device__ __half g_Kh[(size_t)NN * CC * BB];   // K [o][b] fp16
__device__ __half g_Qh[(size_t)NN * CC * BB];   // Q [o][b] fp16
__device__ __half g_Y [(size_t)NN * BB * BB];   // Y [b][k'] fp16, then SM in place
__device__ __half g_Xh[(size_t)NN * CC * BB];   // X fp16 [c][b]
__device__ __half g_Wkh[CC * CC];
__device__ __half g_Wqh[CC * CC];
__device__ float  g_DK2[NN * BB];
__device__ float  g_DQ2[NN * BB];

// ---------------------------------------------------------------------------
__device__ __forceinline__ void cp16s(uint32_t s, const __half* g) {
    asm volatile("cp.async.cg.shared.global [%0], [%1], 16;" :: "r"(s), "l"(g));
}
#define CP_COMMIT() asm volatile("cp.async.commit_group;")

__device__ __forceinline__ void ldm4(uint32_t (&r)[4], uint32_t a) {
    asm volatile("ldmatrix.sync.aligned.m8n8.x4.shared.b16 {%0,%1,%2,%3}, [%4];"
                 : "=r"(r[0]), "=r"(r[1]), "=r"(r[2]), "=r"(r[3]) : "r"(a));
}
__device__ __forceinline__ void ldm4t(uint32_t (&r)[4], uint32_t a) {
    asm volatile("ldmatrix.sync.aligned.m8n8.x4.trans.shared.b16 {%0,%1,%2,%3}, [%4];"
                 : "=r"(r[0]), "=r"(r[1]), "=r"(r[2]), "=r"(r[3]) : "r"(a));
}
__device__ __forceinline__ void mma16(float (&d)[4], const uint32_t (&a)[4],
                                      const uint32_t (&b)[2]) {
    asm volatile(
        "mma.sync.aligned.m16n8k16.row.col.f32.f16.f16.f32 "
        "{%0,%1,%2,%3}, {%4,%5,%6,%7}, {%8,%9}, {%0,%1,%2,%3};"
        : "+f"(d[0]), "+f"(d[1]), "+f"(d[2]), "+f"(d[3])
        : "r"(a[0]), "r"(a[1]), "r"(a[2]), "r"(a[3]), "r"(b[0]), "r"(b[1]));
}

// ===========================================================================
// FP16 warp-MMA GEMM: CTA 128x128, 4 warps (2m x 2n), warp tile 64x64,
// BK=32, 2-stage cp.async, ldmatrix fragment loads (unchanged from R8).
// ===========================================================================
#define BK 32
#define ARM_STR 40
#define KM_STR 136

template <int MODE, int KDIM, bool AKM, typename OutT>
__global__ __launch_bounds__(128, 3)
void gemm_h(const __half* __restrict__ A, int lda, size_t strA,
            const __half* __restrict__ B, int ldb, size_t strB,
            OutT* __restrict__ C, int ldc, size_t strC,
            const float* __restrict__ bias,
            const float* __restrict__ dq2_all,
            const float* __restrict__ dk2_all)
{
    constexpr int SA = AKM ? BK * KM_STR : 128 * ARM_STR;
    constexpr int SB = BK * KM_STR;
    __shared__ __half sA[2][SA];
    __shared__ __half sB[2][SB];
    __shared__ float s_dk[128];

    const int nb = blockIdx.z;
    const __half* An = A + (size_t)nb * strA;
    const __half* Bn = B + (size_t)nb * strB;
    OutT* Cn = C + (size_t)nb * strC;
    const int row0 = blockIdx.y * 128;
    const int col0 = blockIdx.x * 128;

    const int tid = threadIdx.x;
    const int lane = tid & 31;
    const int wid = tid >> 5;
    const int wm = wid >> 1;
    const int wn = wid & 1;
    const int l7 = lane & 7;
    const int g = lane >> 3;

    if (MODE == 1)
        s_dk[tid] = dk2_all[(size_t)nb * BB + col0 + tid];

    float acc[4][8][4] = {};

    auto ldA = [&](int st, int kt) {
        uint32_t sb = (uint32_t)__cvta_generic_to_shared(&sA[st][0]);
        if (!AKM) {
            #pragma unroll
            for (int i = tid; i < 512; i += 128) {
                int m = i >> 2, c = i & 3;
                cp16s(sb + (m * ARM_STR + c * 8) * 2,
                      An + (size_t)(row0 + m) * lda + kt * BK + c * 8);
            }
        } else {
            #pragma unroll
            for (int i = tid; i < 512; i += 128) {
                int k = i >> 4, c = i & 15;
                cp16s(sb + (k * KM_STR + c * 8) * 2,
                      An + (size_t)(kt * BK + k) * lda + row0 + c * 8);
            }
        }
    };
    auto ldB = [&](int st, int kt) {
        uint32_t sb = (uint32_t)__cvta_generic_to_shared(&sB[st][0]);
        #pragma unroll
        for (int i = tid; i < 512; i += 128) {
            int k = i >> 4, c = i & 15;
            cp16s(sb + (k * KM_STR + c * 8) * 2,
                  Bn + (size_t)(kt * BK + k) * ldb + col0 + c * 8);
        }
    };

    constexpr int KT = KDIM / BK;

    ldA(0, 0); ldB(0, 0); CP_COMMIT();

    for (int kt = 0; kt < KT; kt++) {
        const int buf = kt & 1;
        if (kt + 1 < KT) {
            ldA(buf ^ 1, kt + 1);
            ldB(buf ^ 1, kt + 1);
            CP_COMMIT();
            asm volatile("cp.async.wait_group 1;");
        } else {
            asm volatile("cp.async.wait_group 0;");
        }
        __syncthreads();

        uint32_t aA = (uint32_t)__cvta_generic_to_shared(&sA[buf][0]);
        uint32_t aB = (uint32_t)__cvta_generic_to_shared(&sB[buf][0]);

        #pragma unroll
        for (int ks = 0; ks < 2; ks++) {
            uint32_t af[4][4];
            uint32_t bf[8][2];

            #pragma unroll
            for (int mi = 0; mi < 4; mi++) {
                if (!AKM) {
                    int m = wm * 64 + mi * 16 + l7 + (g & 1) * 8;
                    int k = ks * 16 + (g >> 1) * 8;
                    ldm4(af[mi], aA + (m * ARM_STR + k) * 2);
                } else {
                    int k = ks * 16 + (g >> 1) * 8 + l7;
                    int m = wm * 64 + mi * 16 + (g & 1) * 8;
                    ldm4t(af[mi], aA + (k * KM_STR + m) * 2);
                }
            }
            #pragma unroll
            for (int j = 0; j < 4; j++) {
                int k = ks * 16 + (g & 1) * 8 + l7;
                int nn = wn * 64 + j * 16 + (g >> 1) * 8;
                uint32_t r[4];
                ldm4t(r, aB + (k * KM_STR + nn) * 2);
                bf[2 * j][0] = r[0];      bf[2 * j][1] = r[1];
                bf[2 * j + 1][0] = r[2];  bf[2 * j + 1][1] = r[3];
            }
            #pragma unroll
            for (int mi = 0; mi < 4; mi++)
                #pragma unroll
                for (int ni = 0; ni < 8; ni++)
                    mma16(acc[mi][ni], af[mi], bf[ni]);
        }
        __syncthreads();
    }

    // ---- epilogue ----
    const int lr = lane >> 2, lc = lane & 3;
    const float* dq2 = (MODE == 1) ? dq2_all + (size_t)nb * BB : nullptr;

    #pragma unroll
    for (int mi = 0; mi < 4; mi++) {
        const int m = row0 + wm * 64 + mi * 16 + lr;
        float b0 = 0.f, b1 = 0.f, dqa = 0.f, dqb = 0.f;
        if (MODE == 0) { b0 = bias[m]; b1 = bias[m + 8]; }
        if (MODE == 1) { dqa = dq2[m]; dqb = dq2[m + 8]; }

        #pragma unroll
        for (int ni = 0; ni < 8; ni++) {
            const int cl = wn * 64 + ni * 8 + 2 * lc;
            const int nn = col0 + cl;
            float v0 = acc[mi][ni][0], v1 = acc[mi][ni][1];
            float v2 = acc[mi][ni][2], v3 = acc[mi][ni][3];
            if (MODE == 0) {
                v0 += b0; v1 += b0; v2 += b1; v3 += b1;
            } else if (MODE == 1) {
                float dk0 = s_dk[cl], dk1 = s_dk[cl + 1];
                v0 *= rsqrtf(fmaxf(dqa * dk0, EPS));
                v1 *= rsqrtf(fmaxf(dqa * dk1, EPS));
                v2 *= rsqrtf(fmaxf(dqb * dk0, EPS));
                v3 *= rsqrtf(fmaxf(dqb * dk1, EPS));
            }
            if (MODE == 2) {
                float* p0 = (float*)&Cn[(size_t)m * ldc + nn];
                float* p1 = (float*)&Cn[(size_t)(m + 8) * ldc + nn];
                *reinterpret_cast<float2*>(p0) = make_float2(v0, v1);
                *reinterpret_cast<float2*>(p1) = make_float2(v2, v3);
            } else {
                __half* p0 = (__half*)&Cn[(size_t)m * ldc + nn];
                __half* p1 = (__half*)&Cn[(size_t)(m + 8) * ldc + nn];
                *reinterpret_cast<__half2*>(p0) = __floats2half2_rn(v0, v1);
                *reinterpret_cast<__half2*>(p1) = __floats2half2_rn(v2, v3);
            }
        }
    }
}

// ---------------------------------------------------------------------------
__global__ __launch_bounds__(256)
void to_half_kernel(const float* __restrict__ in, __half* __restrict__ out, int n4)
{
    int i = blockIdx.x * 256 + threadIdx.x;
    int stride = gridDim.x * 256;
    for (; i < n4; i += stride) {
        float4 v = reinterpret_cast<const float4*>(in)[i];
        __half2* o = reinterpret_cast<__half2*>(out) + 2 * i;
        o[0] = __floats2half2_rn(v.x, v.y);
        o[1] = __floats2half2_rn(v.z, v.w);
    }
}

// ---------------------------------------------------------------------------
// Column squared norms of K and Q — full-chip grid.
// Block: 32 half2-columns (64 b) of one n; 8 warps split the c-loop (128 c
// each); smem reduction. Grid = (BB/64, NN) = (32, 8) = 256 blocks.
// ---------------------------------------------------------------------------
__global__ __launch_bounds__(256)
void sq_kernel()
{
    __shared__ float rkx[8][32], rky[8][32], rqx[8][32], rqy[8][32];
    const int n = blockIdx.y;
    const int col = threadIdx.x & 31;           // half2 column within block
    const int sp = threadIdx.x >> 5;            // c-split 0..7
    const int b2 = blockIdx.x * 32 + col;       // global half2 column

    const __half2* Kn = (const __half2*)(g_Kh + (size_t)n * CC * BB) + b2;
    const __half2* Qn = (const __half2*)(g_Qh + (size_t)n * CC * BB) + b2;

    float skx = 0.f, sky = 0.f, sqx = 0.f, sqy = 0.f;
    const int c0 = sp * (CC / 8);
    #pragma unroll 8
    for (int c = c0; c < c0 + CC / 8; c++) {
        float2 k2 = __half22float2(Kn[(size_t)c * (BB / 2)]);
        float2 q2 = __half22float2(Qn[(size_t)c * (BB / 2)]);
        skx = fmaf(k2.x, k2.x, skx); sky = fmaf(k2.y, k2.y, sky);
        sqx = fmaf(q2.x, q2.x, sqx); sqy = fmaf(q2.y, q2.y, sqy);
    }
    rkx[sp][col] = skx; rky[sp][col] = sky;
    rqx[sp][col] = sqx; rqy[sp][col] = sqy;
    __syncthreads();

    if (threadIdx.x < 32) {
        float tkx = 0.f, tky = 0.f, tqx = 0.f, tqy = 0.f;
        #pragma unroll
        for (int s = 0; s < 8; s++) {
            tkx += rkx[s][col]; tky += rky[s][col];
            tqx += rqx[s][col]; tqy += rqy[s][col];
        }
        const int b = n * BB + 2 * b2;
        g_DK2[b] = tkx;  g_DK2[b + 1] = tky;
        g_DQ2[b] = tqx;  g_DQ2[b + 1] = tqy;
    }
}

// ---------------------------------------------------------------------------
// exp(x) for |x| <= ~1.05 via Taylor to x^9 (rel err ~3e-7) — pure FMA.
// ---------------------------------------------------------------------------
__device__ __forceinline__ float exp_poly(float x)
{
    float r = fmaf(x, 1.f / 9.f, 1.f);
    r = fmaf(r * x, 1.f / 8.f, 1.f);
    r = fmaf(r * x, 1.f / 7.f, 1.f);
    r = fmaf(r * x, 1.f / 6.f, 1.f);
    r = fmaf(r * x, 1.f / 5.f, 1.f);
    r = fmaf(r * x, 1.f / 4.f, 1.f);
    r = fmaf(r * x, 1.f / 3.f, 1.f);
    r = fmaf(r * x, 0.5f, 1.f);
    return fmaf(r, x, 1.f);
}

// ---------------------------------------------------------------------------
// Softmax over b (axis=1) of Y[n][b][k'], fp16, no max-shift — full-chip grid.
// Block: 32 half2-columns of one n; 8 warps split the b-loop (256 b each).
// Pass 1: partial exp-sums -> smem reduce -> inv. Pass 2: recompute + write.
// Grid = (BB/64, NN) = (32, 8) = 256 blocks.
// ---------------------------------------------------------------------------
__global__ __launch_bounds__(256)
void softmax_kernel()
{
    __shared__ float rsx[8][32], rsy[8][32];
    __shared__ float invx[32], invy[32];
    const int n = blockIdx.y;
    const int col = threadIdx.x & 31;
    const int sp = threadIdx.x >> 5;
    const int k2 = blockIdx.x * 32 + col;

    __half2* Yn = (__half2*)(g_Y + (size_t)n * BB * BB) + k2;
    const int b0 = sp * (BB / 8);

    float sx = 0.f, sy = 0.f;
    #pragma unroll 4
    for (int b = b0; b < b0 + BB / 8; b++) {
        float2 v = __half22float2(Yn[(size_t)b * (BB / 2)]);
        sx += exp_poly(v.x);
        sy += exp_poly(v.y);
    }
    rsx[sp][col] = sx; rsy[sp][col] = sy;
    __syncthreads();

    if (threadIdx.x < 32) {
        float tx = 0.f, ty = 0.f;
        #pragma unroll
        for (int s = 0; s < 8; s++) { tx += rsx[s][col]; ty += rsy[s][col]; }
        invx[col] = 1.f / tx;
        invy[col] = 1.f / ty;
    }
    __syncthreads();

    const float ix = invx[col], iy = invy[col];
    #pragma unroll 4
    for (int b = b0; b < b0 + BB / 8; b++) {
        float2 v = __half22float2(Yn[(size_t)b * (BB / 2)]);
        Yn[(size_t)b * (BB / 2)] =
            __floats2half2_rn(exp_poly(v.x) * ix, exp_poly(v.y) * iy);
    }
}

// ---------------------------------------------------------------------------
extern "C" void kernel_launch(void* const* d_in, const int* in_sizes, int n_in,
                              void* d_out, int out_size)
{
    const float* X    = (const float*)d_in[0];
    const float* Wk_w = (const float*)d_in[1];
    const float* Wk_b = (const float*)d_in[2];
    const float* Wq_w = (const float*)d_in[3];
    const float* Wq_b = (const float*)d_in[4];
    float* Z = (float*)d_out;

    __half* Kh;  cudaGetSymbolAddress((void**)&Kh,  g_Kh);
    __half* Qh;  cudaGetSymbolAddress((void**)&Qh,  g_Qh);
    __half* Yd;  cudaGetSymbolAddress((void**)&Yd,  g_Y);
    __half* Xh;  cudaGetSymbolAddress((void**)&Xh,  g_Xh);
    __half* Wkh; cudaGetSymbolAddress((void**)&Wkh, g_Wkh);
    __half* Wqh; cudaGetSymbolAddress((void**)&Wqh, g_Wqh);
    float* DK2;  cudaGetSymbolAddress((void**)&DK2, g_DK2);
    float* DQ2;  cudaGetSymbolAddress((void**)&DQ2, g_DQ2);

    const size_t sXn = (size_t)CC * BB;
    const size_t sYn = (size_t)BB * BB;

    // 0) convert operands to fp16
    to_half_kernel<<<2048, 256>>>(X, Xh, (int)(NN * sXn / 4));
    to_half_kernel<<<256, 256>>>(Wk_w, Wkh, CC * CC / 4);
    to_half_kernel<<<256, 256>>>(Wq_w, Wqh, CC * CC / 4);

    // 1) projections: K/Q[o][b] = W[o][c] @ X[c][b] + bias
    gemm_h<0, CC, false, __half><<<dim3(BB / 128, CC / 128, NN), 128>>>(
        Wkh, CC, 0, Xh, BB, sXn, Kh, BB, sXn, Wk_b, nullptr, nullptr);
    gemm_h<0, CC, false, __half><<<dim3(BB / 128, CC / 128, NN), 128>>>(
        Wqh, CC, 0, Xh, BB, sXn, Qh, BB, sXn, Wq_b, nullptr, nullptr);

    // 2) squared norms (full-chip grid)
    sq_kernel<<<dim3(BB / 64, NN), 256>>>();

    // 3) scores: Y[b][k'] = sum_c Q[c][b] K[c][k'] * rsqrt(dq2[b] dk2[k'])
    gemm_h<1, CC, true, __half><<<dim3(BB / 128, BB / 128, NN), 128>>>(
        Qh, BB, sXn, Kh, BB, sXn, Yd, BB, sYn, nullptr, DQ2, DK2);

    // 4) softmax over b (query axis), in place (full-chip grid)
    softmax_kernel<<<dim3(BB / 64, NN), 256>>>();

    // 5) mix: Z[c][k'] = sum_b X[c][b] SM[b][k']
    gemm_h<2, BB, false, float><<<dim3(BB / 128, CC / 128, NN), 128>>>(
        Xh, BB, sXn, Yd, BB, sYn, Z, BB, sXn, nullptr, nullptr, nullptr);
}